// round 9
// baseline (speedup 1.0000x reference)
#include <cuda_runtime.h>
#include <cstdint>

// ---------------- configuration ----------------
#define H1_BINS   8192          // top 13 bits of monotone key
#define LOW_BITS  19
#define LOW_BINS  (1u << LOW_BITS)
#define MAX_SLOTS 32

// ---------------- static scratch (no allocations allowed) ----------------
__device__ __align__(16) unsigned int  g_hist1[H1_BINS];
__device__ __align__(16) unsigned int  g_hist2[(size_t)MAX_SLOTS * LOW_BINS]; // 64 MB
__device__ __align__(16) unsigned char g_lut[H1_BINS];
__device__ int          g_tbin[32];
__device__ unsigned int g_trr[32];
__device__ int          g_tslot[32];
__device__ int          g_nslots;
__device__ float        g_tval[32];
__device__ float        g_cut[16];
__device__ float2       g_mnstep[16];

// order-preserving float32 <-> uint32 key
__device__ __forceinline__ unsigned int mono_key(float f) {
    unsigned int b = __float_as_uint(f);
    unsigned int m = (unsigned int)(((int)b) >> 31) | 0x80000000u;
    return b ^ m;
}
__device__ __forceinline__ float unmono_key(unsigned int k) {
    unsigned int b = (k & 0x80000000u) ? (k & 0x7FFFFFFFu) : ~k;
    return __uint_as_float(b);
}

// ---------------- pass 1: coarse histogram (top 13 bits) ----------------
__global__ void __launch_bounds__(256) k_hist1(const float4* __restrict__ x, int n4) {
    __shared__ unsigned int sh[H1_BINS];
    for (int i = threadIdx.x; i < H1_BINS; i += blockDim.x) sh[i] = 0u;
    __syncthreads();
    int stride = gridDim.x * blockDim.x;
    for (int i = blockIdx.x * blockDim.x + threadIdx.x; i < n4; i += stride) {
        float4 v = x[i];
        atomicAdd(&sh[mono_key(v.x) >> LOW_BITS], 1u);
        atomicAdd(&sh[mono_key(v.y) >> LOW_BITS], 1u);
        atomicAdd(&sh[mono_key(v.z) >> LOW_BITS], 1u);
        atomicAdd(&sh[mono_key(v.w) >> LOW_BITS], 1u);
    }
    __syncthreads();
    for (int i = threadIdx.x; i < H1_BINS; i += blockDim.x) {
        unsigned int c = sh[i];
        if (c) atomicAdd(&g_hist1[i], c);
    }
}

// ---------------- scan coarse histogram, locate target bins ----------------
__global__ void __launch_bounds__(1024) k_scan1(unsigned int n) {
    __shared__ unsigned int pre[H1_BINS];
    __shared__ unsigned int wsum[32];
    __shared__ int          sbin[32];
    __shared__ unsigned int srr[32];
    __shared__ int          sslot[32];

    int t = threadIdx.x;
    int lane = t & 31, w = t >> 5;
    unsigned base = (unsigned)t * 8u;
    unsigned run = 0;
    unsigned vals[8];
#pragma unroll
    for (int k = 0; k < 8; k++) { run += g_hist1[base + k]; vals[k] = run; }
    unsigned tot = run;
    unsigned inc = tot;
#pragma unroll
    for (int o = 1; o < 32; o <<= 1) {
        unsigned u = __shfl_up_sync(0xFFFFFFFFu, inc, o);
        if (lane >= o) inc += u;
    }
    if (lane == 31) wsum[w] = inc;
    __syncthreads();
    if (t < 32) {
        unsigned v = wsum[t], s = v;
#pragma unroll
        for (int o = 1; o < 32; o <<= 1) {
            unsigned u = __shfl_up_sync(0xFFFFFFFFu, s, o);
            if (t >= o) s += u;
        }
        wsum[t] = s - v;   // exclusive warp offsets
    }
    __syncthreads();
    unsigned off = wsum[w] + (inc - tot);
#pragma unroll
    for (int k = 0; k < 8; k++) pre[base + k] = vals[k] + off;  // inclusive cumsum
    __syncthreads();

    if (t < 32) {
        unsigned S = n >> 4;
        unsigned r;
        if (t == 0)       r = 0u;
        else if (t == 31) r = n - 1u;
        else {
            unsigned c = (unsigned)(t + 1) >> 1;        // 1..15
            r = c * S - ((t & 1) ? 1u : 0u);            // odd t -> c*S-1, even t -> c*S
        }
        int lo = 0, hi = H1_BINS - 1;
        while (lo < hi) { int mid = (lo + hi) >> 1; if (pre[mid] > r) hi = mid; else lo = mid + 1; }
        sbin[t] = lo;
        srr[t]  = r - (lo ? pre[lo - 1] : 0u);
    }
    __syncthreads();

    // zero LUT in parallel; dedup bins -> slots on thread 0
    for (int i = t; i < H1_BINS; i += 1024) g_lut[i] = 0;
    if (t == 0) {
        int ns = 0;
        for (int i = 0; i < 32; i++) {
            int s = -1;
            for (int j = 0; j < i; j++) if (sbin[j] == sbin[i]) { s = sslot[j]; break; }
            if (s < 0) s = ns++;
            sslot[i] = s;
        }
        g_nslots = ns;
    }
    __syncthreads();
    if (t == 0) {
        for (int i = 0; i < 32; i++) g_lut[sbin[i]] = (unsigned char)(sslot[i] + 1);
    }
    if (t < 32) { g_tbin[t] = sbin[t]; g_trr[t] = srr[t]; g_tslot[t] = sslot[t]; }
    __syncthreads();
    // self-zero hist1 for the next graph replay
    for (int i = t; i < H1_BINS; i += 1024) g_hist1[i] = 0u;
}

// ---------------- pass 2: fine histogram (low 19 bits) for cut bins ----------------
__global__ void __launch_bounds__(256) k_hist2(const float4* __restrict__ x, int n4) {
    __shared__ unsigned char lut[H1_BINS];
    {
        const uint4* src = (const uint4*)g_lut;
        uint4* dst = (uint4*)lut;
        for (int i = threadIdx.x; i < H1_BINS / 16; i += blockDim.x) dst[i] = src[i];
    }
    __syncthreads();
    int stride = gridDim.x * blockDim.x;
    for (int i = blockIdx.x * blockDim.x + threadIdx.x; i < n4; i += stride) {
        float4 v = x[i];
        unsigned k0 = mono_key(v.x), k1 = mono_key(v.y), k2 = mono_key(v.z), k3 = mono_key(v.w);
        unsigned char s0 = lut[k0 >> LOW_BITS];
        unsigned char s1 = lut[k1 >> LOW_BITS];
        unsigned char s2 = lut[k2 >> LOW_BITS];
        unsigned char s3 = lut[k3 >> LOW_BITS];
        if (s0) atomicAdd(&g_hist2[(size_t)(s0 - 1) * LOW_BINS + (k0 & (LOW_BINS - 1u))], 1u);
        if (s1) atomicAdd(&g_hist2[(size_t)(s1 - 1) * LOW_BINS + (k1 & (LOW_BINS - 1u))], 1u);
        if (s2) atomicAdd(&g_hist2[(size_t)(s2 - 1) * LOW_BINS + (k2 & (LOW_BINS - 1u))], 1u);
        if (s3) atomicAdd(&g_hist2[(size_t)(s3 - 1) * LOW_BINS + (k3 & (LOW_BINS - 1u))], 1u);
    }
}

// ---------------- scan fine histograms -> exact cut values ----------------
__global__ void __launch_bounds__(1024) k_scan2() {
    __shared__ unsigned int wsum[32];
    int t = blockIdx.x;                    // target 0..31
    int slot = g_tslot[t];
    unsigned rr = g_trr[t];
    unsigned bin = (unsigned)g_tbin[t];
    const uint4* h = (const uint4*)(g_hist2 + (size_t)slot * LOW_BINS);

    int tid = threadIdx.x, lane = tid & 31, w = tid >> 5;
    int b4 = tid * 128;                    // 128 uint4 = 512 bins per thread
    unsigned sum = 0;
    for (int i = 0; i < 128; i++) {
        uint4 u = h[b4 + i];
        sum += u.x + u.y + u.z + u.w;
    }
    unsigned inc = sum;
#pragma unroll
    for (int o = 1; o < 32; o <<= 1) {
        unsigned u = __shfl_up_sync(0xFFFFFFFFu, inc, o);
        if (lane >= o) inc += u;
    }
    if (lane == 31) wsum[w] = inc;
    __syncthreads();
    if (tid < 32) {
        unsigned v = wsum[tid], s = v;
#pragma unroll
        for (int o = 1; o < 32; o <<= 1) {
            unsigned u = __shfl_up_sync(0xFFFFFFFFu, s, o);
            if (tid >= o) s += u;
        }
        wsum[tid] = s - v;
    }
    __syncthreads();
    unsigned excl = wsum[w] + (inc - sum);
    if (rr >= excl && rr < excl + sum) {
        unsigned run = excl;
        unsigned low = 0;
        bool found = false;
        for (int i = 0; i < 128 && !found; i++) {
            uint4 u = h[b4 + i];
            unsigned vv[4] = { u.x, u.y, u.z, u.w };
#pragma unroll
            for (int j = 0; j < 4; j++) {
                if (!found) {
                    if (rr < run + vv[j]) { low = ((unsigned)(b4 + i)) * 4u + (unsigned)j; found = true; }
                    else run += vv[j];
                }
            }
        }
        unsigned key = (bin << LOW_BITS) | low;
        g_tval[t] = unmono_key(key);
    }
}

// ---------------- zero used hist2 slots for next replay ----------------
__global__ void __launch_bounds__(256) k_zero2() {
    unsigned total4 = (unsigned)g_nslots * (LOW_BINS / 4u);
    uint4* p = (uint4*)g_hist2;
    uint4 z = make_uint4(0u, 0u, 0u, 0u);
    unsigned stride = gridDim.x * blockDim.x;
    for (unsigned i = blockIdx.x * blockDim.x + threadIdx.x; i < total4; i += stride) p[i] = z;
}

// ---------------- build per-chunk params ----------------
__global__ void k_params() {
    int c = threadIdx.x;
    if (c < 16) {
        float mn = (c == 0)  ? g_tval[0]  : g_tval[2 * c];
        float mx = (c == 15) ? g_tval[31] : g_tval[2 * c + 1];
        float step = __fdiv_rn(__fsub_rn(mx, mn), 15.0f);
        g_mnstep[c] = make_float2(mn, step);
        g_cut[c] = (c == 0) ? __int_as_float(0xFF800000) : mn;   // -inf sentinel
    }
}

// ---------------- final quantize pass ----------------
__device__ __forceinline__ float quant_one(float v, const float* cut, const float2* ms) {
    int c = (v >= cut[8]) ? 8 : 0;
    if (v >= cut[c + 4]) c += 4;
    if (v >= cut[c + 2]) c += 2;
    if (v >= cut[c + 1]) c += 1;
    float2 p = ms[c];
    float tq = __fdiv_rn(__fsub_rn(v, p.x), p.y);
    float q  = __fadd_rn(__fmul_rn(rintf(tq), p.y), p.x);
    return (p.y == 0.0f) ? v : q;     // mn == mx -> pass through
}

__global__ void __launch_bounds__(256) k_quant(const float4* __restrict__ x,
                                               float4* __restrict__ o, int n4) {
    __shared__ float  s_cut[16];
    __shared__ float2 s_ms[16];
    if (threadIdx.x < 16) { s_cut[threadIdx.x] = g_cut[threadIdx.x]; s_ms[threadIdx.x] = g_mnstep[threadIdx.x]; }
    __syncthreads();
    int stride = gridDim.x * blockDim.x;
    for (int i = blockIdx.x * blockDim.x + threadIdx.x; i < n4; i += stride) {
        float4 v = x[i];
        float4 r;
        r.x = quant_one(v.x, s_cut, s_ms);
        r.y = quant_one(v.y, s_cut, s_ms);
        r.z = quant_one(v.z, s_cut, s_ms);
        r.w = quant_one(v.w, s_cut, s_ms);
        o[i] = r;
    }
}

// ---------------- launcher ----------------
extern "C" void kernel_launch(void* const* d_in, const int* in_sizes, int n_in,
                              void* d_out, int out_size) {
    const float4* x = (const float4*)d_in[0];
    float4* out = (float4*)d_out;
    int n = in_sizes[0];
    int n4 = n / 4;                          // n = 16*2048*2048, divisible by 16

    k_hist1 <<< 888, 256  >>> (x, n4);       // coarse histogram
    k_scan1 <<< 1,   1024 >>> ((unsigned)n); // locate cut bins, build LUT, self-zero hist1
    k_hist2 <<< 1184, 256 >>> (x, n4);       // fine histogram of cut bins
    k_scan2 <<< 32,  1024 >>> ();            // exact order statistics
    k_zero2 <<< 592, 256  >>> ();            // re-zero used hist2 slots (replay invariant)
    k_params<<< 1,   32   >>> ();            // per-chunk mn/step + cuts
    k_quant <<< 1184, 256 >>> (x, out, n4);  // elementwise quantize
}

// round 10
// speedup vs baseline: 1.1935x; 1.1935x over previous
#include <cuda_runtime.h>
#include <cstdint>

// ---------------- configuration ----------------
#define H1_BINS   8192          // top 13 bits of monotone key
#define LOW_BITS  19
#define LOW_BINS  (1u << LOW_BITS)
#define MAX_SLOTS 32
#define NSEG      128
#define SEG_BINS  (LOW_BINS / NSEG)   // 4096 bins = 16 KB per segment

// ---------------- static scratch (no allocations allowed) ----------------
__device__ __align__(16) unsigned int  g_hist1[H1_BINS];
__device__ __align__(16) unsigned int  g_hist2[(size_t)MAX_SLOTS * LOW_BINS]; // 64 MB
__device__ __align__(16) unsigned int  g_part[MAX_SLOTS][NSEG];
__device__ __align__(16) unsigned char g_lut[H1_BINS];
__device__ int          g_tbin[32];
__device__ unsigned int g_trr[32];
__device__ int          g_tslot[32];
__device__ int          g_nslots;
__device__ float        g_tval[32];
__device__ float        g_cut[16];
__device__ float2       g_mnstep[16];

// order-preserving float32 <-> uint32 key
__device__ __forceinline__ unsigned int mono_key(float f) {
    unsigned int b = __float_as_uint(f);
    unsigned int m = (unsigned int)(((int)b) >> 31) | 0x80000000u;
    return b ^ m;
}
__device__ __forceinline__ float unmono_key(unsigned int k) {
    unsigned int b = (k & 0x80000000u) ? (k & 0x7FFFFFFFu) : ~k;
    return __uint_as_float(b);
}

// ---------------- pass 1: coarse histogram (top 13 bits) ----------------
__global__ void __launch_bounds__(256) k_hist1(const float4* __restrict__ x, int n4) {
    __shared__ unsigned int sh[H1_BINS];
    for (int i = threadIdx.x; i < H1_BINS; i += blockDim.x) sh[i] = 0u;
    __syncthreads();
    int stride = gridDim.x * blockDim.x;
    for (int i = blockIdx.x * blockDim.x + threadIdx.x; i < n4; i += stride) {
        float4 v = x[i];
        atomicAdd(&sh[mono_key(v.x) >> LOW_BITS], 1u);
        atomicAdd(&sh[mono_key(v.y) >> LOW_BITS], 1u);
        atomicAdd(&sh[mono_key(v.z) >> LOW_BITS], 1u);
        atomicAdd(&sh[mono_key(v.w) >> LOW_BITS], 1u);
    }
    __syncthreads();
    for (int i = threadIdx.x; i < H1_BINS; i += blockDim.x) {
        unsigned int c = sh[i];
        if (c) atomicAdd(&g_hist1[i], c);
    }
}

// ---------------- scan coarse histogram, locate target bins ----------------
__global__ void __launch_bounds__(1024) k_scan1(unsigned int n) {
    __shared__ unsigned int pre[H1_BINS];
    __shared__ unsigned int wsum[32];
    __shared__ int          sbin[32];
    __shared__ unsigned int srr[32];
    __shared__ int          sslot[32];

    int t = threadIdx.x;
    int lane = t & 31, w = t >> 5;
    unsigned base = (unsigned)t * 8u;
    unsigned run = 0;
    unsigned vals[8];
#pragma unroll
    for (int k = 0; k < 8; k++) { run += g_hist1[base + k]; vals[k] = run; }
    unsigned tot = run;
    unsigned inc = tot;
#pragma unroll
    for (int o = 1; o < 32; o <<= 1) {
        unsigned u = __shfl_up_sync(0xFFFFFFFFu, inc, o);
        if (lane >= o) inc += u;
    }
    if (lane == 31) wsum[w] = inc;
    __syncthreads();
    if (t < 32) {
        unsigned v = wsum[t], s = v;
#pragma unroll
        for (int o = 1; o < 32; o <<= 1) {
            unsigned u = __shfl_up_sync(0xFFFFFFFFu, s, o);
            if (t >= o) s += u;
        }
        wsum[t] = s - v;   // exclusive warp offsets
    }
    __syncthreads();
    unsigned off = wsum[w] + (inc - tot);
#pragma unroll
    for (int k = 0; k < 8; k++) pre[base + k] = vals[k] + off;  // inclusive cumsum
    __syncthreads();

    if (t < 32) {
        unsigned S = n >> 4;
        unsigned r;
        if (t == 0)       r = 0u;
        else if (t == 31) r = n - 1u;
        else {
            unsigned c = (unsigned)(t + 1) >> 1;        // 1..15
            r = c * S - ((t & 1) ? 1u : 0u);            // odd t -> c*S-1, even t -> c*S
        }
        int lo = 0, hi = H1_BINS - 1;
        while (lo < hi) { int mid = (lo + hi) >> 1; if (pre[mid] > r) hi = mid; else lo = mid + 1; }
        sbin[t] = lo;
        srr[t]  = r - (lo ? pre[lo - 1] : 0u);
    }
    __syncthreads();

    // zero LUT in parallel; dedup bins -> slots on thread 0
    for (int i = t; i < H1_BINS; i += 1024) g_lut[i] = 0;
    if (t == 0) {
        int ns = 0;
        for (int i = 0; i < 32; i++) {
            int s = -1;
            for (int j = 0; j < i; j++) if (sbin[j] == sbin[i]) { s = sslot[j]; break; }
            if (s < 0) s = ns++;
            sslot[i] = s;
        }
        g_nslots = ns;
    }
    __syncthreads();
    if (t == 0) {
        for (int i = 0; i < 32; i++) g_lut[sbin[i]] = (unsigned char)(sslot[i] + 1);
    }
    if (t < 32) { g_tbin[t] = sbin[t]; g_trr[t] = srr[t]; g_tslot[t] = sslot[t]; }
    __syncthreads();
    // self-zero hist1 for the next graph replay
    for (int i = t; i < H1_BINS; i += 1024) g_hist1[i] = 0u;
}

// ---------------- pass 2: fine histogram (low 19 bits) for cut bins ----------------
__global__ void __launch_bounds__(256) k_hist2(const float4* __restrict__ x, int n4) {
    __shared__ unsigned char lut[H1_BINS];
    {
        const uint4* src = (const uint4*)g_lut;
        uint4* dst = (uint4*)lut;
        for (int i = threadIdx.x; i < H1_BINS / 16; i += blockDim.x) dst[i] = src[i];
    }
    __syncthreads();
    int stride = gridDim.x * blockDim.x;
    for (int i = blockIdx.x * blockDim.x + threadIdx.x; i < n4; i += stride) {
        float4 v = x[i];
        unsigned k0 = mono_key(v.x), k1 = mono_key(v.y), k2 = mono_key(v.z), k3 = mono_key(v.w);
        unsigned char s0 = lut[k0 >> LOW_BITS];
        unsigned char s1 = lut[k1 >> LOW_BITS];
        unsigned char s2 = lut[k2 >> LOW_BITS];
        unsigned char s3 = lut[k3 >> LOW_BITS];
        if (s0) atomicAdd(&g_hist2[(size_t)(s0 - 1) * LOW_BINS + (k0 & (LOW_BINS - 1u))], 1u);
        if (s1) atomicAdd(&g_hist2[(size_t)(s1 - 1) * LOW_BINS + (k1 & (LOW_BINS - 1u))], 1u);
        if (s2) atomicAdd(&g_hist2[(size_t)(s2 - 1) * LOW_BINS + (k2 & (LOW_BINS - 1u))], 1u);
        if (s3) atomicAdd(&g_hist2[(size_t)(s3 - 1) * LOW_BINS + (k3 & (LOW_BINS - 1u))], 1u);
    }
}

// ---------------- scan2a: per-segment partial sums (full-chip parallel) ----------------
__global__ void __launch_bounds__(256) k_scan2a() {
    int slot = blockIdx.x / NSEG;
    if (slot >= g_nslots) return;
    int seg = blockIdx.x % NSEG;
    const uint4* h = (const uint4*)(g_hist2 + (size_t)slot * LOW_BINS + (size_t)seg * SEG_BINS);
    int t = threadIdx.x;
    unsigned s = 0;
#pragma unroll
    for (int i = 0; i < 4; i++) {               // 4 uint4 = 16 bins per thread
        uint4 u = h[t * 4 + i];
        s += u.x + u.y + u.z + u.w;
    }
#pragma unroll
    for (int o = 16; o; o >>= 1) s += __shfl_down_sync(0xFFFFFFFFu, s, o);
    __shared__ unsigned ws[8];
    if ((t & 31) == 0) ws[t >> 5] = s;
    __syncthreads();
    if (t < 8) {
        unsigned v = ws[t];
#pragma unroll
        for (int o = 4; o; o >>= 1) v += __shfl_down_sync(0xFFu, v, o, 8);
        if (t == 0) g_part[slot][seg] = v;
    }
}

// ---------------- scan2b: locate exact bin per target ----------------
__global__ void __launch_bounds__(128) k_scan2b() {
    int t = blockIdx.x;                    // target 0..31
    int slot = g_tslot[t];
    unsigned rr = g_trr[t];
    unsigned bin = (unsigned)g_tbin[t];
    int tid = threadIdx.x;

    __shared__ unsigned s[NSEG];
    __shared__ int s_seg;
    __shared__ unsigned s_rr2;

    // scan the 128 partial sums to find the segment containing rank rr
    unsigned p = g_part[slot][tid];
    s[tid] = p; __syncthreads();
    for (int o = 1; o < NSEG; o <<= 1) {
        unsigned v = (tid >= o) ? s[tid - o] : 0u;
        __syncthreads();
        s[tid] += v;
        __syncthreads();
    }
    unsigned incl = s[tid], excl = incl - p;
    if (rr >= excl && rr < incl) { s_seg = tid; s_rr2 = rr - excl; }
    __syncthreads();
    int seg = s_seg;
    unsigned rr2 = s_rr2;

    // scan that single 4096-bin segment (16 KB, L2-hot)
    const uint4* h = (const uint4*)(g_hist2 + (size_t)slot * LOW_BINS + (size_t)seg * SEG_BINS);
    uint4 u[8];
    unsigned sum = 0;
#pragma unroll
    for (int i = 0; i < 8; i++) {               // 32 bins per thread
        u[i] = h[tid * 8 + i];
        sum += u[i].x + u[i].y + u[i].z + u[i].w;
    }
    s[tid] = sum; __syncthreads();
    for (int o = 1; o < 128; o <<= 1) {
        unsigned v = (tid >= o) ? s[tid - o] : 0u;
        __syncthreads();
        s[tid] += v;
        __syncthreads();
    }
    unsigned incl2 = s[tid], excl2 = incl2 - sum;
    if (rr2 >= excl2 && rr2 < incl2) {
        unsigned run = excl2;
        unsigned low = 0;
        bool found = false;
        for (int i = 0; i < 8 && !found; i++) {
            unsigned vv[4] = { u[i].x, u[i].y, u[i].z, u[i].w };
            for (int j = 0; j < 4; j++) {
                if (!found) {
                    if (rr2 < run + vv[j]) { low = (unsigned)(tid * 32 + i * 4 + j); found = true; }
                    else run += vv[j];
                }
            }
        }
        unsigned key = (bin << LOW_BITS) | ((unsigned)seg * SEG_BINS + low);
        g_tval[t] = unmono_key(key);
    }
}

// ---------------- zero used hist2 slots for next replay ----------------
__global__ void __launch_bounds__(256) k_zero2() {
    unsigned total4 = (unsigned)g_nslots * (LOW_BINS / 4u);
    uint4* p = (uint4*)g_hist2;
    uint4 z = make_uint4(0u, 0u, 0u, 0u);
    unsigned stride = gridDim.x * blockDim.x;
    for (unsigned i = blockIdx.x * blockDim.x + threadIdx.x; i < total4; i += stride) p[i] = z;
}

// ---------------- build per-chunk params ----------------
__global__ void k_params() {
    int c = threadIdx.x;
    if (c < 16) {
        float mn = (c == 0)  ? g_tval[0]  : g_tval[2 * c];
        float mx = (c == 15) ? g_tval[31] : g_tval[2 * c + 1];
        float step = __fdiv_rn(__fsub_rn(mx, mn), 15.0f);
        g_mnstep[c] = make_float2(mn, step);
        g_cut[c] = (c == 0) ? __int_as_float(0xFF800000) : mn;   // -inf sentinel
    }
}

// ---------------- final quantize pass ----------------
__device__ __forceinline__ float quant_one(float v, const float* cut, const float2* ms) {
    int c = (v >= cut[8]) ? 8 : 0;
    if (v >= cut[c + 4]) c += 4;
    if (v >= cut[c + 2]) c += 2;
    if (v >= cut[c + 1]) c += 1;
    float2 p = ms[c];
    float tq = __fdiv_rn(__fsub_rn(v, p.x), p.y);
    float q  = __fadd_rn(__fmul_rn(rintf(tq), p.y), p.x);
    return (p.y == 0.0f) ? v : q;     // mn == mx -> pass through
}

__global__ void __launch_bounds__(256) k_quant(const float4* __restrict__ x,
                                               float4* __restrict__ o, int n4) {
    __shared__ float  s_cut[16];
    __shared__ float2 s_ms[16];
    if (threadIdx.x < 16) { s_cut[threadIdx.x] = g_cut[threadIdx.x]; s_ms[threadIdx.x] = g_mnstep[threadIdx.x]; }
    __syncthreads();
    int stride = gridDim.x * blockDim.x;
    for (int i = blockIdx.x * blockDim.x + threadIdx.x; i < n4; i += stride) {
        float4 v = x[i];
        float4 r;
        r.x = quant_one(v.x, s_cut, s_ms);
        r.y = quant_one(v.y, s_cut, s_ms);
        r.z = quant_one(v.z, s_cut, s_ms);
        r.w = quant_one(v.w, s_cut, s_ms);
        o[i] = r;
    }
}

// ---------------- launcher ----------------
extern "C" void kernel_launch(void* const* d_in, const int* in_sizes, int n_in,
                              void* d_out, int out_size) {
    const float4* x = (const float4*)d_in[0];
    float4* out = (float4*)d_out;
    int n = in_sizes[0];
    int n4 = n / 4;                               // n = 16*2048*2048, divisible by 16

    k_hist1  <<< 1184, 256 >>> (x, n4);           // coarse histogram
    k_scan1  <<< 1,   1024 >>> ((unsigned)n);     // locate cut bins, build LUT, self-zero hist1
    k_hist2  <<< 1184, 256 >>> (x, n4);           // fine histogram of cut bins
    k_scan2a <<< MAX_SLOTS * NSEG, 256 >>> ();    // per-segment partial sums (full chip)
    k_scan2b <<< 32,  128 >>> ();                 // exact order statistics (L2-hot)
    k_zero2  <<< 592, 256 >>> ();                 // re-zero used hist2 slots (replay invariant)
    k_params <<< 1,   32  >>> ();                 // per-chunk mn/step + cuts
    k_quant  <<< 1184, 256 >>> (x, out, n4);      // elementwise quantize
}